// round 4
// baseline (speedup 1.0000x reference)
#include <cuda_runtime.h>
#include <math.h>

// ---------------- problem constants ----------------
#define BATCH   32
#define NN      96          // N_NODES == LATENT
#define H1D     512
#define H2D     1024
#define LDEC    4
#define NSQ     9216        // 96*96

// d_out layout: x_output[32*9216], y_output[32], z[32*96], log_q[32*96]
#define X_OFF   0
#define Y_OFF   294912
#define Z_OFF   294944
#define LQ_OFF  298016

#define KS1     18          // split-K for enc1 (K=9216 -> chunks of 512)
#define KS2     8           // split-K for enc2 (K=1024 -> chunks of 128)

// ---------------- device scratch (no allocations allowed) ----------------
__device__ float g_part1[KS1 * BATCH * H2D];
__device__ float g_h1  [BATCH * H2D];
__device__ float g_part2[KS2 * BATCH * H1D];
__device__ float g_h2  [BATCH * H1D];
__device__ float g_mu  [BATCH * NN];
__device__ float g_lv  [BATCH * NN];
__device__ float g_z   [BATCH * NN];
__device__ float g_eps [BATCH * NN];
__device__ float g_d   [LDEC * BATCH * NN];
__device__ float g_gg  [LDEC * BATCH * NN];
__device__ float g_pre [BATCH * NSQ];

// ---------------- threefry2x32 (JAX PRNG, key=42, PARTITIONABLE stream) ----------------
#define TF_ROUND(x0, x1, r) do { x0 += x1; x1 = (x1 << (r)) | (x1 >> (32 - (r))); x1 ^= x0; } while (0)

__device__ __forceinline__ float bits_to_normal(unsigned b) {
    // jax.random.uniform: u in [0,1) from top 23 bits
    float u = __uint_as_float(0x3F800000u | (b >> 9)) - 1.0f;
    const float lo = __uint_as_float(0xBF7FFFFFu);   // nextafter(-1, 0)
    // (hi - lo) rounds to exactly 2.0f in f32
    float v = u * 2.0f + lo;
    v = fmaxf(v, lo);
    return 1.41421354f * erfinvf(v);                 // float32(sqrt(2)) * erfinv
}

// jax_threefry_partitionable=True (modern default):
//   per element i: counter (hi=0, lo=i); (out0, out1) = threefry2x32(key, (0, i))
//   for bit_width <= 32 the partitionable path returns out0 ^ out1
__global__ void eps_kernel(float* __restrict__ eps) {
    int i = blockIdx.x * blockDim.x + threadIdx.x;
    if (i >= BATCH * NN) return;
    const unsigned ks0 = 0u, ks1 = 42u;
    const unsigned ks2 = 0x1BD11BDAu ^ ks0 ^ ks1;
    unsigned x0 = 0u + ks0;             // high 32 bits of counter = 0
    unsigned x1 = (unsigned)i + ks1;    // low 32 bits of counter = i

    TF_ROUND(x0,x1,13); TF_ROUND(x0,x1,15); TF_ROUND(x0,x1,26); TF_ROUND(x0,x1,6);
    x0 += ks1; x1 += ks2 + 1u;
    TF_ROUND(x0,x1,17); TF_ROUND(x0,x1,29); TF_ROUND(x0,x1,16); TF_ROUND(x0,x1,24);
    x0 += ks2; x1 += ks0 + 2u;
    TF_ROUND(x0,x1,13); TF_ROUND(x0,x1,15); TF_ROUND(x0,x1,26); TF_ROUND(x0,x1,6);
    x0 += ks0; x1 += ks1 + 3u;
    TF_ROUND(x0,x1,17); TF_ROUND(x0,x1,29); TF_ROUND(x0,x1,16); TF_ROUND(x0,x1,24);
    x0 += ks1; x1 += ks2 + 4u;
    TF_ROUND(x0,x1,13); TF_ROUND(x0,x1,15); TF_ROUND(x0,x1,26); TF_ROUND(x0,x1,6);
    x0 += ks2; x1 += ks0 + 5u;

    eps[i] = bits_to_normal(x0 ^ x1);   // XOR of the two output words
}

// ---------------- split-K GEMM: C_part[s][b][n] = sum_k A[b][k] * W[n][k] ----------------
__global__ void gemm_tn_splitk(const float* __restrict__ A, const float* __restrict__ W,
                               float* __restrict__ part, int N, int K, int kchunk)
{
    const int BN = 64, BK = 32;
    const int n0 = blockIdx.x * BN;
    const int s  = blockIdx.y;
    const int kb = s * kchunk;
    const int ke = kb + kchunk;

    __shared__ __align__(16) float As[32][36];       // [k][b]
    __shared__ __align__(16) float Ws[32][66];       // [k][c]

    const int tid = threadIdx.x;          // 256
    const int cx  = tid & 31;             // -> columns 2cx, 2cx+1
    const int by  = tid >> 5;             // -> batches 4by..4by+3
    const int kk  = tid & 31;
    const int rr  = tid >> 5;

    float acc[4][2] = {};

    for (int k0 = kb; k0 < ke; k0 += BK) {
        __syncthreads();
        #pragma unroll
        for (int i = 0; i < 4; i++)
            As[kk][rr + 8*i] = A[(rr + 8*i) * K + k0 + kk];
        #pragma unroll
        for (int i = 0; i < BN/8; i++)
            Ws[kk][rr + 8*i] = W[(size_t)(n0 + rr + 8*i) * K + k0 + kk];
        __syncthreads();
        #pragma unroll
        for (int t = 0; t < BK; t++) {
            float4 a = *(const float4*)&As[t][4*by];
            float2 w = *(const float2*)&Ws[t][2*cx];
            acc[0][0] = fmaf(a.x, w.x, acc[0][0]);
            acc[0][1] = fmaf(a.x, w.y, acc[0][1]);
            acc[1][0] = fmaf(a.y, w.x, acc[1][0]);
            acc[1][1] = fmaf(a.y, w.y, acc[1][1]);
            acc[2][0] = fmaf(a.z, w.x, acc[2][0]);
            acc[2][1] = fmaf(a.z, w.y, acc[2][1]);
            acc[3][0] = fmaf(a.w, w.x, acc[3][0]);
            acc[3][1] = fmaf(a.w, w.y, acc[3][1]);
        }
    }
    #pragma unroll
    for (int i = 0; i < 4; i++)
        #pragma unroll
        for (int j = 0; j < 2; j++)
            part[((size_t)s * BATCH + 4*by + i) * N + n0 + 2*cx + j] = acc[i][j];
}

template<bool RELU>
__global__ void reduce_act(const float* __restrict__ part, int S,
                           const float* __restrict__ bias, float* __restrict__ out, int N)
{
    int idx = blockIdx.x * 256 + threadIdx.x;
    if (idx >= BATCH * N) return;
    int n = idx % N;
    float a = bias[n];
    for (int s = 0; s < S; s++) a += part[(size_t)s * BATCH * N + idx];
    out[idx] = RELU ? fmaxf(a, 0.0f) : a;
}

// ---------------- group-conditioned mu/logvar heads ----------------
__global__ void heads_kernel(const float* __restrict__ h2, const float* __restrict__ c,
                             const float* __restrict__ mu0w, const float* __restrict__ mu0b,
                             const float* __restrict__ lv0w, const float* __restrict__ lv0b,
                             const float* __restrict__ mu1w, const float* __restrict__ mu1b,
                             const float* __restrict__ lv1w, const float* __restrict__ lv1b,
                             float* __restrict__ mu, float* __restrict__ lv)
{
    int w = blockIdx.x * (blockDim.x >> 5) + (threadIdx.x >> 5);
    int lane = threadIdx.x & 31;
    if (w >= BATCH * 2 * NN) return;
    int b = w / (2 * NN);
    int r = w % (2 * NN);
    int which = r / NN;         // 0 = mu, 1 = logvar
    int n = r % NN;
    bool is0 = (c[b] == 0.0f);
    const float* wp = which == 0 ? (is0 ? mu0w : mu1w) : (is0 ? lv0w : lv1w);
    const float* bp = which == 0 ? (is0 ? mu0b : mu1b) : (is0 ? lv0b : lv1b);
    const float* hr = h2 + b * H1D;
    const float* wr = wp + n * H1D;
    float acc = 0.0f;
    #pragma unroll 4
    for (int k = lane; k < H1D; k += 32) acc = fmaf(hr[k], wr[k], acc);
    #pragma unroll
    for (int o = 16; o; o >>= 1) acc += __shfl_xor_sync(0xFFFFFFFFu, acc, o);
    if (lane == 0) (which ? lv : mu)[b * NN + n] = acc + bp[n];
}

// ---------------- reparameterize + z/log_q outputs ----------------
__global__ void reparam_kernel(const float* __restrict__ mu, const float* __restrict__ lv,
                               const float* __restrict__ eps,
                               float* __restrict__ z_scr, float* __restrict__ out)
{
    int i = blockIdx.x * blockDim.x + threadIdx.x;
    if (i >= BATCH * NN) return;
    float m = mu[i], v = lv[i], e = eps[i];
    float sd = expf(0.5f * v);
    float z = fmaf(e, sd, m);
    z_scr[i] = z;
    out[Z_OFF  + i] = z;
    out[LQ_OFF + i] = fmaf(-0.5f * e, e, -0.5f * v) - 0.91893853320467274f;
}

// ---------------- y regression (reads z scratch; one warp per row) ----------------
__global__ void y_kernel(const float* __restrict__ z, const float* __restrict__ c,
                         const float* __restrict__ reg_w, const float* __restrict__ reg_b,
                         float* __restrict__ out)
{
    int b = blockIdx.x;
    int lane = threadIdx.x;          // 32 threads
    float s = 0.0f;
    #pragma unroll
    for (int l = lane; l < NN; l += 32) s = fmaf(z[b*NN + l], reg_w[l], s);
    #pragma unroll
    for (int o = 16; o; o >>= 1) s += __shfl_xor_sync(0xFFFFFFFFu, s, o);
    if (lane == 0) out[Y_OFF + b] = s + c[b] * reg_w[NN] + reg_b[0];
}

// ---------------- decoder: d[k,b,n] = sigmoid(z[b] . dec_w[k,n,:] + dec_b[k,n]) ----------------
__global__ void dec_kernel(const float* __restrict__ z, const float* __restrict__ dec_w,
                           const float* __restrict__ dec_b, float* __restrict__ d)
{
    int k = blockIdx.x, b = blockIdx.y, n = threadIdx.x;  // 96 threads
    __shared__ float zs[NN];
    zs[n] = z[b*NN + n];
    __syncthreads();
    const float* wr = dec_w + (k*NN + n) * NN;
    float acc = dec_b[k*NN + n];
    #pragma unroll 8
    for (int l = 0; l < NN; l++) acc = fmaf(zs[l], wr[l], acc);
    d[(k*BATCH + b)*NN + n] = 1.0f / (1.0f + expf(-acc));
}

// ---------------- graphconv (group-selected) ----------------
__global__ void gc_kernel(const float* __restrict__ d, const float* __restrict__ c,
                          const float* __restrict__ gc0w, const float* __restrict__ gc0b,
                          const float* __restrict__ gc1w, const float* __restrict__ gc1b,
                          float* __restrict__ g)
{
    int k = blockIdx.x, b = blockIdx.y, m = threadIdx.x;
    __shared__ float ds[NN];
    ds[m] = d[(k*BATCH + b)*NN + m];
    __syncthreads();
    bool is0 = (c[b] == 0.0f);
    const float* wr = (is0 ? gc0w : gc1w) + (k*NN + m) * NN;
    const float* bp = is0 ? gc0b : gc1b;
    float acc = bp[k*NN + m];
    #pragma unroll 8
    for (int n = 0; n < NN; n++) acc = fmaf(ds[n], wr[n], acc);
    g[(k*BATCH + b)*NN + m] = 1.0f / (1.0f + expf(-acc));
}

// ---------------- pre[b, i*96+j] = b_sel + sum_k W_sel[k] g[k,b,i] g[k,b,j] ----------------
__global__ void outer_kernel(const float* __restrict__ g, const float* __restrict__ c,
                             const float* __restrict__ W0, const float* __restrict__ b0v,
                             const float* __restrict__ W1, const float* __restrict__ b1v,
                             float* __restrict__ pre)
{
    int b = blockIdx.x, tid = threadIdx.x;   // 256 threads
    __shared__ float gi[LDEC][NN];
    __shared__ float wg[LDEC][NN];
    bool is0 = (c[b] == 0.0f);
    const float* Wsel = is0 ? W0 : W1;
    const float* bsel = is0 ? b0v : b1v;
    for (int idx = tid; idx < LDEC * NN; idx += 256) {
        int k = idx / NN, n = idx % NN;
        float gv = g[(k*BATCH + b)*NN + n];
        gi[k][n] = gv;
        wg[k][n] = gv * Wsel[k];
    }
    __syncthreads();
    for (int idx = tid; idx < NSQ; idx += 256) {
        int i = idx / NN, j = idx % NN;
        float v = bsel[idx];
        #pragma unroll
        for (int k = 0; k < LDEC; k++) v = fmaf(wg[k][i], gi[k][j], v);
        pre[(size_t)b * NSQ + idx] = v;
    }
}

// ---------------- big fc GEMM + exp epilogue: x[b][n] = exp(pre[b].fc_w[n,:] + fc_b[n]) --------
__global__ void gemm_fc(const float* __restrict__ A, const float* __restrict__ W,
                        const float* __restrict__ bias, float* __restrict__ xout)
{
    const int BN = 64, BK = 32, K = NSQ;
    const int n0 = blockIdx.x * BN;

    __shared__ __align__(16) float As[32][36];
    __shared__ __align__(16) float Ws[32][66];

    const int tid = threadIdx.x;
    const int cx  = tid & 31;
    const int by  = tid >> 5;
    const int kk  = tid & 31;
    const int rr  = tid >> 5;

    float acc[4][2] = {};

    for (int k0 = 0; k0 < K; k0 += BK) {
        __syncthreads();
        #pragma unroll
        for (int i = 0; i < 4; i++)
            As[kk][rr + 8*i] = A[(rr + 8*i) * K + k0 + kk];
        #pragma unroll
        for (int i = 0; i < BN/8; i++)
            Ws[kk][rr + 8*i] = W[(size_t)(n0 + rr + 8*i) * K + k0 + kk];
        __syncthreads();
        #pragma unroll
        for (int t = 0; t < BK; t++) {
            float4 a = *(const float4*)&As[t][4*by];
            float2 w = *(const float2*)&Ws[t][2*cx];
            acc[0][0] = fmaf(a.x, w.x, acc[0][0]);
            acc[0][1] = fmaf(a.x, w.y, acc[0][1]);
            acc[1][0] = fmaf(a.y, w.x, acc[1][0]);
            acc[1][1] = fmaf(a.y, w.y, acc[1][1]);
            acc[2][0] = fmaf(a.z, w.x, acc[2][0]);
            acc[2][1] = fmaf(a.z, w.y, acc[2][1]);
            acc[3][0] = fmaf(a.w, w.x, acc[3][0]);
            acc[3][1] = fmaf(a.w, w.y, acc[3][1]);
        }
    }
    #pragma unroll
    for (int i = 0; i < 4; i++)
        #pragma unroll
        for (int j = 0; j < 2; j++) {
            int n = n0 + 2*cx + j;
            int b = 4*by + i;
            xout[(size_t)b * NSQ + n] = expf(acc[i][j] + bias[n]);
        }
}

// ---------------- launch ----------------
extern "C" void kernel_launch(void* const* d_in, const int* in_sizes, int n_in,
                              void* d_out, int out_size)
{
    const float* x_in   = (const float*)d_in[0];
    const float* c_in   = (const float*)d_in[1];
    const float* enc_w1 = (const float*)d_in[2];
    const float* enc_b1 = (const float*)d_in[3];
    const float* enc_w2 = (const float*)d_in[4];
    const float* enc_b2 = (const float*)d_in[5];
    const float* mu0_w  = (const float*)d_in[6];
    const float* mu0_b  = (const float*)d_in[7];
    const float* lv0_w  = (const float*)d_in[8];
    const float* lv0_b  = (const float*)d_in[9];
    const float* mu1_w  = (const float*)d_in[10];
    const float* mu1_b  = (const float*)d_in[11];
    const float* lv1_w  = (const float*)d_in[12];
    const float* lv1_b  = (const float*)d_in[13];
    const float* dec_w  = (const float*)d_in[14];
    const float* dec_b  = (const float*)d_in[15];
    const float* gc0_w  = (const float*)d_in[16];
    const float* gc0_b  = (const float*)d_in[17];
    const float* gc1_w  = (const float*)d_in[18];
    const float* gc1_b  = (const float*)d_in[19];
    const float* fc_w   = (const float*)d_in[20];
    const float* fc_b   = (const float*)d_in[21];
    const float* reg_w  = (const float*)d_in[22];
    const float* reg_b  = (const float*)d_in[23];
    const float* W0     = (const float*)d_in[24];
    const float* b0v    = (const float*)d_in[25];
    const float* W1     = (const float*)d_in[26];
    const float* b1v    = (const float*)d_in[27];
    float* out = (float*)d_out;

    void *p;
    float *part1, *h1, *part2, *h2, *mu, *lv, *z, *eps, *dbuf, *gbuf, *pre;
    cudaGetSymbolAddress(&p, g_part1); part1 = (float*)p;
    cudaGetSymbolAddress(&p, g_h1);    h1    = (float*)p;
    cudaGetSymbolAddress(&p, g_part2); part2 = (float*)p;
    cudaGetSymbolAddress(&p, g_h2);    h2    = (float*)p;
    cudaGetSymbolAddress(&p, g_mu);    mu    = (float*)p;
    cudaGetSymbolAddress(&p, g_lv);    lv    = (float*)p;
    cudaGetSymbolAddress(&p, g_z);     z     = (float*)p;
    cudaGetSymbolAddress(&p, g_eps);   eps   = (float*)p;
    cudaGetSymbolAddress(&p, g_d);     dbuf  = (float*)p;
    cudaGetSymbolAddress(&p, g_gg);    gbuf  = (float*)p;
    cudaGetSymbolAddress(&p, g_pre);   pre   = (float*)p;

    // noise (independent of everything else)
    eps_kernel<<<12, 256>>>(eps);

    // encoder
    gemm_tn_splitk<<<dim3(H2D/64, KS1), 256>>>(x_in, enc_w1, part1, H2D, NSQ, NSQ/KS1);
    reduce_act<true><<<(BATCH*H2D + 255)/256, 256>>>(part1, KS1, enc_b1, h1, H2D);
    gemm_tn_splitk<<<dim3(H1D/64, KS2), 256>>>(h1, enc_w2, part2, H1D, H2D, H2D/KS2);
    reduce_act<true><<<(BATCH*H1D + 255)/256, 256>>>(part2, KS2, enc_b2, h2, H1D);

    // group-conditioned heads: 32*2*96 = 6144 warp-dot-products
    heads_kernel<<<768, 256>>>(h2, c_in, mu0_w, mu0_b, lv0_w, lv0_b,
                               mu1_w, mu1_b, lv1_w, lv1_b, mu, lv);

    // reparameterize (+ writes z, log_q)
    reparam_kernel<<<12, 256>>>(mu, lv, eps, z, out);

    // y regression
    y_kernel<<<BATCH, 32>>>(z, c_in, reg_w, reg_b, out);

    // decoder chain
    dec_kernel<<<dim3(LDEC, BATCH), NN>>>(z, dec_w, dec_b, dbuf);
    gc_kernel<<<dim3(LDEC, BATCH), NN>>>(dbuf, c_in, gc0_w, gc0_b, gc1_w, gc1_b, gbuf);
    outer_kernel<<<BATCH, 256>>>(gbuf, c_in, W0, b0v, W1, b1v, pre);

    // single group-selected fc GEMM + exp  (reference computes both groups; we select per row)
    gemm_fc<<<NSQ/64, 256>>>(pre, fc_w, fc_b, out + X_OFF);
}

// round 5
// speedup vs baseline: 2.0550x; 2.0550x over previous
#include <cuda_runtime.h>
#include <math.h>

// ---------------- problem constants ----------------
#define BATCH   32
#define NN      96          // N_NODES == LATENT
#define H1D     512
#define H2D     1024
#define LDEC    4
#define NSQ     9216        // 96*96

// d_out layout: x_output[32*9216], y_output[32], z[32*96], log_q[32*96]
#define X_OFF   0
#define Y_OFF   294912
#define Z_OFF   294944
#define LQ_OFF  298016

#define KS1     36          // split-K for enc1 (K=9216 -> chunks of 256)
#define KS2     16          // split-K for enc2 (K=1024 -> chunks of 64)

// ---- fc GEMM config ----
#define FCBN    256         // cols per block
#define FCBK    64          // k per tile
#define FCKS    4           // k splits
#define FCKCH   (NSQ / FCKS)    // 2304
#define FCTILES (FCKCH / FCBK)  // 36
#define WS_STRIDE 69            // W smem row stride (words); 5*lane bank walk -> conflict free
#define AS_STRIDE 36            // A smem row stride (words); 144B -> 16B aligned rows
#define WS_WORDS (FCBN * WS_STRIDE)   // 17664
#define AS_WORDS (FCBK * AS_STRIDE)   // 2304
#define FC_SMEM_BYTES ((2 * WS_WORDS + 2 * AS_WORDS) * 4)   // 159744

// ---------------- device scratch (no allocations allowed) ----------------
__device__ float g_part1[KS1 * BATCH * H2D];
__device__ float g_h1  [BATCH * H2D];
__device__ float g_part2[KS2 * BATCH * H1D];
__device__ float g_h2  [BATCH * H1D];
__device__ float g_mu  [BATCH * NN];
__device__ float g_lv  [BATCH * NN];
__device__ float g_z   [BATCH * NN];
__device__ float g_eps [BATCH * NN];
__device__ float g_d   [LDEC * BATCH * NN];
__device__ float g_gg  [LDEC * BATCH * NN];
__device__ float g_pre [BATCH * NSQ];
__device__ float g_pfc [FCKS * BATCH * NSQ];

// ---------------- threefry2x32 (JAX PRNG, key=42, PARTITIONABLE stream) ----------------
#define TF_ROUND(x0, x1, r) do { x0 += x1; x1 = (x1 << (r)) | (x1 >> (32 - (r))); x1 ^= x0; } while (0)

__device__ __forceinline__ float bits_to_normal(unsigned b) {
    float u = __uint_as_float(0x3F800000u | (b >> 9)) - 1.0f;
    const float lo = __uint_as_float(0xBF7FFFFFu);
    float v = u * 2.0f + lo;
    v = fmaxf(v, lo);
    return 1.41421354f * erfinvf(v);
}

__global__ void eps_kernel(float* __restrict__ eps) {
    int i = blockIdx.x * blockDim.x + threadIdx.x;
    if (i >= BATCH * NN) return;
    const unsigned ks0 = 0u, ks1 = 42u;
    const unsigned ks2 = 0x1BD11BDAu ^ ks0 ^ ks1;
    unsigned x0 = 0u + ks0;
    unsigned x1 = (unsigned)i + ks1;

    TF_ROUND(x0,x1,13); TF_ROUND(x0,x1,15); TF_ROUND(x0,x1,26); TF_ROUND(x0,x1,6);
    x0 += ks1; x1 += ks2 + 1u;
    TF_ROUND(x0,x1,17); TF_ROUND(x0,x1,29); TF_ROUND(x0,x1,16); TF_ROUND(x0,x1,24);
    x0 += ks2; x1 += ks0 + 2u;
    TF_ROUND(x0,x1,13); TF_ROUND(x0,x1,15); TF_ROUND(x0,x1,26); TF_ROUND(x0,x1,6);
    x0 += ks0; x1 += ks1 + 3u;
    TF_ROUND(x0,x1,17); TF_ROUND(x0,x1,29); TF_ROUND(x0,x1,16); TF_ROUND(x0,x1,24);
    x0 += ks1; x1 += ks2 + 4u;
    TF_ROUND(x0,x1,13); TF_ROUND(x0,x1,15); TF_ROUND(x0,x1,26); TF_ROUND(x0,x1,6);
    x0 += ks2; x1 += ks0 + 5u;

    eps[i] = bits_to_normal(x0 ^ x1);   // partitionable: out0 ^ out1
}

// ---------------- split-K GEMM (encoder): C_part[s][b][n] = sum_k A[b][k] * W[n][k] -------
__global__ void gemm_tn_splitk(const float* __restrict__ A, const float* __restrict__ W,
                               float* __restrict__ part, int N, int K, int kchunk)
{
    const int BN = 64, BK = 32;
    const int n0 = blockIdx.x * BN;
    const int s  = blockIdx.y;
    const int kb = s * kchunk;
    const int ke = kb + kchunk;

    __shared__ __align__(16) float As[32][36];
    __shared__ __align__(16) float Ws[32][66];

    const int tid = threadIdx.x;          // 256
    const int cx  = tid & 31;
    const int by  = tid >> 5;
    const int kk  = tid & 31;
    const int rr  = tid >> 5;

    float acc[4][2] = {};

    for (int k0 = kb; k0 < ke; k0 += BK) {
        __syncthreads();
        #pragma unroll
        for (int i = 0; i < 4; i++)
            As[kk][rr + 8*i] = A[(rr + 8*i) * K + k0 + kk];
        #pragma unroll
        for (int i = 0; i < BN/8; i++)
            Ws[kk][rr + 8*i] = W[(size_t)(n0 + rr + 8*i) * K + k0 + kk];
        __syncthreads();
        #pragma unroll
        for (int t = 0; t < BK; t++) {
            float4 a = *(const float4*)&As[t][4*by];
            float2 w = *(const float2*)&Ws[t][2*cx];
            acc[0][0] = fmaf(a.x, w.x, acc[0][0]);
            acc[0][1] = fmaf(a.x, w.y, acc[0][1]);
            acc[1][0] = fmaf(a.y, w.x, acc[1][0]);
            acc[1][1] = fmaf(a.y, w.y, acc[1][1]);
            acc[2][0] = fmaf(a.z, w.x, acc[2][0]);
            acc[2][1] = fmaf(a.z, w.y, acc[2][1]);
            acc[3][0] = fmaf(a.w, w.x, acc[3][0]);
            acc[3][1] = fmaf(a.w, w.y, acc[3][1]);
        }
    }
    #pragma unroll
    for (int i = 0; i < 4; i++)
        #pragma unroll
        for (int j = 0; j < 2; j++)
            part[((size_t)s * BATCH + 4*by + i) * N + n0 + 2*cx + j] = acc[i][j];
}

template<bool RELU>
__global__ void reduce_act(const float* __restrict__ part, int S,
                           const float* __restrict__ bias, float* __restrict__ out, int N)
{
    int idx = blockIdx.x * 256 + threadIdx.x;
    if (idx >= BATCH * N) return;
    int n = idx % N;
    float a = bias[n];
    for (int s = 0; s < S; s++) a += part[(size_t)s * BATCH * N + idx];
    out[idx] = RELU ? fmaxf(a, 0.0f) : a;
}

// ---------------- group-conditioned mu/logvar heads ----------------
__global__ void heads_kernel(const float* __restrict__ h2, const float* __restrict__ c,
                             const float* __restrict__ mu0w, const float* __restrict__ mu0b,
                             const float* __restrict__ lv0w, const float* __restrict__ lv0b,
                             const float* __restrict__ mu1w, const float* __restrict__ mu1b,
                             const float* __restrict__ lv1w, const float* __restrict__ lv1b,
                             float* __restrict__ mu, float* __restrict__ lv)
{
    int w = blockIdx.x * (blockDim.x >> 5) + (threadIdx.x >> 5);
    int lane = threadIdx.x & 31;
    if (w >= BATCH * 2 * NN) return;
    int b = w / (2 * NN);
    int r = w % (2 * NN);
    int which = r / NN;
    int n = r % NN;
    bool is0 = (c[b] == 0.0f);
    const float* wp = which == 0 ? (is0 ? mu0w : mu1w) : (is0 ? lv0w : lv1w);
    const float* bp = which == 0 ? (is0 ? mu0b : mu1b) : (is0 ? lv0b : lv1b);
    const float* hr = h2 + b * H1D;
    const float* wr = wp + n * H1D;
    float acc = 0.0f;
    #pragma unroll 4
    for (int k = lane; k < H1D; k += 32) acc = fmaf(hr[k], wr[k], acc);
    #pragma unroll
    for (int o = 16; o; o >>= 1) acc += __shfl_xor_sync(0xFFFFFFFFu, acc, o);
    if (lane == 0) (which ? lv : mu)[b * NN + n] = acc + bp[n];
}

// ---------------- reparameterize + z/log_q outputs ----------------
__global__ void reparam_kernel(const float* __restrict__ mu, const float* __restrict__ lv,
                               const float* __restrict__ eps,
                               float* __restrict__ z_scr, float* __restrict__ out)
{
    int i = blockIdx.x * blockDim.x + threadIdx.x;
    if (i >= BATCH * NN) return;
    float m = mu[i], v = lv[i], e = eps[i];
    float sd = expf(0.5f * v);
    float z = fmaf(e, sd, m);
    z_scr[i] = z;
    out[Z_OFF  + i] = z;
    out[LQ_OFF + i] = fmaf(-0.5f * e, e, -0.5f * v) - 0.91893853320467274f;
}

// ---------------- y regression ----------------
__global__ void y_kernel(const float* __restrict__ z, const float* __restrict__ c,
                         const float* __restrict__ reg_w, const float* __restrict__ reg_b,
                         float* __restrict__ out)
{
    int b = blockIdx.x;
    int lane = threadIdx.x;
    float s = 0.0f;
    #pragma unroll
    for (int l = lane; l < NN; l += 32) s = fmaf(z[b*NN + l], reg_w[l], s);
    #pragma unroll
    for (int o = 16; o; o >>= 1) s += __shfl_xor_sync(0xFFFFFFFFu, s, o);
    if (lane == 0) out[Y_OFF + b] = s + c[b] * reg_w[NN] + reg_b[0];
}

// ---------------- decoder ----------------
__global__ void dec_kernel(const float* __restrict__ z, const float* __restrict__ dec_w,
                           const float* __restrict__ dec_b, float* __restrict__ d)
{
    int k = blockIdx.x, b = blockIdx.y, n = threadIdx.x;
    __shared__ float zs[NN];
    zs[n] = z[b*NN + n];
    __syncthreads();
    const float* wr = dec_w + (k*NN + n) * NN;
    float acc = dec_b[k*NN + n];
    #pragma unroll 8
    for (int l = 0; l < NN; l++) acc = fmaf(zs[l], wr[l], acc);
    d[(k*BATCH + b)*NN + n] = 1.0f / (1.0f + expf(-acc));
}

// ---------------- graphconv (group-selected) ----------------
__global__ void gc_kernel(const float* __restrict__ d, const float* __restrict__ c,
                          const float* __restrict__ gc0w, const float* __restrict__ gc0b,
                          const float* __restrict__ gc1w, const float* __restrict__ gc1b,
                          float* __restrict__ g)
{
    int k = blockIdx.x, b = blockIdx.y, m = threadIdx.x;
    __shared__ float ds[NN];
    ds[m] = d[(k*BATCH + b)*NN + m];
    __syncthreads();
    bool is0 = (c[b] == 0.0f);
    const float* wr = (is0 ? gc0w : gc1w) + (k*NN + m) * NN;
    const float* bp = is0 ? gc0b : gc1b;
    float acc = bp[k*NN + m];
    #pragma unroll 8
    for (int n = 0; n < NN; n++) acc = fmaf(ds[n], wr[n], acc);
    g[(k*BATCH + b)*NN + m] = 1.0f / (1.0f + expf(-acc));
}

// ---------------- pre[b, i*96+j] = b_sel + sum_k W_sel[k] g[k,b,i] g[k,b,j] ----------------
__global__ void outer_kernel(const float* __restrict__ g, const float* __restrict__ c,
                             const float* __restrict__ W0, const float* __restrict__ b0v,
                             const float* __restrict__ W1, const float* __restrict__ b1v,
                             float* __restrict__ pre)
{
    int b = blockIdx.x, tid = threadIdx.x;
    __shared__ float gi[LDEC][NN];
    __shared__ float wg[LDEC][NN];
    bool is0 = (c[b] == 0.0f);
    const float* Wsel = is0 ? W0 : W1;
    const float* bsel = is0 ? b0v : b1v;
    for (int idx = tid; idx < LDEC * NN; idx += 256) {
        int k = idx / NN, n = idx % NN;
        float gv = g[(k*BATCH + b)*NN + n];
        gi[k][n] = gv;
        wg[k][n] = gv * Wsel[k];
    }
    __syncthreads();
    for (int idx = tid; idx < NSQ; idx += 256) {
        int i = idx / NN, j = idx % NN;
        float v = bsel[idx];
        #pragma unroll
        for (int k = 0; k < LDEC; k++) v = fmaf(wg[k][i], gi[k][j], v);
        pre[(size_t)b * NSQ + idx] = v;
    }
}

// ---------------- big fc GEMM: split-K, f32x2 packed FMA, double-buffered ----------------
// part[s][b][n] = sum_{k in chunk s} pre[b][k] * fc_w[n][k]
// block: 256 threads, tile 32b x 256c, BK=64. warp = (bg=wid>>1)->8 batches, (cg=wid&1)->128 cols
// thread: 4 batch-pairs x 4 cols (cols strided by 32 for conflict-free W reads)
__global__ void __launch_bounds__(256, 1)
gemm_fc_split(const float* __restrict__ A, const float* __restrict__ W,
              float* __restrict__ part)
{
    extern __shared__ float sm[];
    float* WsBuf0 = sm;
    float* WsBuf1 = sm + WS_WORDS;
    float* AsBuf0 = sm + 2*WS_WORDS;
    float* AsBuf1 = sm + 2*WS_WORDS + AS_WORDS;

    const int tid  = threadIdx.x;
    const int lane = tid & 31;
    const int wid  = tid >> 5;
    const int n0   = blockIdx.x * FCBN;
    const int kb   = blockIdx.y * FCKCH;

    const int bg = wid >> 1;              // batch group 0..3 (8 batches each)
    const int cg = wid & 1;               // col half
    const int cbase = cg * 128 + lane;    // + 32*cc

    float4 wst[16];
    float4 ast[2];
    unsigned long long acc[4][4];
    #pragma unroll
    for (int i = 0; i < 4; i++)
        #pragma unroll
        for (int j = 0; j < 4; j++) acc[i][j] = 0ULL;

    auto load_tile = [&](int kt) {
        const float* wb = W + (size_t)kb + (size_t)kt * FCBK;
        #pragma unroll
        for (int it = 0; it < 16; it++) {
            int idx = it*256 + tid;
            int c = idx >> 4, k4 = idx & 15;          // lanes 0-15: same c, k4=lane
            wst[it] = *(const float4*)(wb + (size_t)(n0 + c) * NSQ + 4*k4);
        }
        const float* ab = A + (size_t)lane * NSQ + kb + kt * FCBK;
        #pragma unroll
        for (int it = 0; it < 2; it++) {
            int k4 = 8*it + wid;                      // lane = batch row (uncoalesced, L2-resident)
            ast[it] = *(const float4*)(ab + 4*k4);
        }
    };

    auto store_tile = [&](float* ws, float* as) {
        #pragma unroll
        for (int it = 0; it < 16; it++) {
            int idx = it*256 + tid;
            int c = idx >> 4, k4 = idx & 15;
            float* p = ws + c * WS_STRIDE + 4*k4;     // W kept [c][k]
            p[0] = wst[it].x; p[1] = wst[it].y; p[2] = wst[it].z; p[3] = wst[it].w;
        }
        #pragma unroll
        for (int it = 0; it < 2; it++) {
            int k4 = 8*it + wid;
            float* p = as + (4*k4) * AS_STRIDE + lane; // A transposed [k][b]; lane=b -> conflict free
            p[0]           = ast[it].x;
            p[AS_STRIDE]   = ast[it].y;
            p[2*AS_STRIDE] = ast[it].z;
            p[3*AS_STRIDE] = ast[it].w;
        }
    };

    auto compute_tile = [&](const float* ws, const float* as) {
        const float* arow  = as + 8*bg;
        const float* wcol0 = ws + cbase * WS_STRIDE;
        #pragma unroll 8
        for (int kk = 0; kk < FCBK; kk++) {
            // A: 8 batches = 4 pairs, broadcast (all lanes same addr), 16B-aligned
            ulonglong2 a01 = *(const ulonglong2*)(arow + kk * AS_STRIDE);
            ulonglong2 a23 = *(const ulonglong2*)(arow + kk * AS_STRIDE + 4);
            unsigned long long ap0 = a01.x, ap1 = a01.y, ap2 = a23.x, ap3 = a23.y;
            #pragma unroll
            for (int cc = 0; cc < 4; cc++) {
                float wv = wcol0[cc * 32 * WS_STRIDE + kk];
                unsigned long long wd;
                asm("mov.b64 %0, {%1, %1};" : "=l"(wd) : "r"(__float_as_uint(wv)));
                asm("fma.rn.f32x2 %0, %1, %2, %0;" : "+l"(acc[0][cc]) : "l"(ap0), "l"(wd));
                asm("fma.rn.f32x2 %0, %1, %2, %0;" : "+l"(acc[1][cc]) : "l"(ap1), "l"(wd));
                asm("fma.rn.f32x2 %0, %1, %2, %0;" : "+l"(acc[2][cc]) : "l"(ap2), "l"(wd));
                asm("fma.rn.f32x2 %0, %1, %2, %0;" : "+l"(acc[3][cc]) : "l"(ap3), "l"(wd));
            }
        }
    };

    load_tile(0);
    store_tile(WsBuf0, AsBuf0);

    for (int t = 0; t < FCTILES; t++) {
        __syncthreads();
        if (t + 1 < FCTILES) load_tile(t + 1);
        if (t & 1) compute_tile(WsBuf1, AsBuf1);
        else       compute_tile(WsBuf0, AsBuf0);
        if (t + 1 < FCTILES) {
            if ((t + 1) & 1) store_tile(WsBuf1, AsBuf1);
            else             store_tile(WsBuf0, AsBuf0);
        }
    }

    // epilogue: write partials
    float* pbase = part + (size_t)blockIdx.y * BATCH * NSQ;
    #pragma unroll
    for (int bp = 0; bp < 4; bp++) {
        #pragma unroll
        for (int cc = 0; cc < 4; cc++) {
            unsigned lo, hi;
            asm("mov.b64 {%0, %1}, %2;" : "=r"(lo), "=r"(hi) : "l"(acc[bp][cc]));
            int b0 = bg*8 + 2*bp;
            int n  = n0 + cbase + 32*cc;
            pbase[(size_t)b0 * NSQ + n]       = __uint_as_float(lo);
            pbase[(size_t)(b0 + 1) * NSQ + n] = __uint_as_float(hi);
        }
    }
}

__global__ void fc_combine(const float* __restrict__ part, const float* __restrict__ bias,
                           float* __restrict__ xout)
{
    int idx = blockIdx.x * 256 + threadIdx.x;
    if (idx >= BATCH * NSQ) return;
    int n = idx % NSQ;
    float a = bias[n];
    #pragma unroll
    for (int s = 0; s < FCKS; s++) a += part[(size_t)s * BATCH * NSQ + idx];
    xout[idx] = expf(a);
}

// ---------------- launch ----------------
extern "C" void kernel_launch(void* const* d_in, const int* in_sizes, int n_in,
                              void* d_out, int out_size)
{
    const float* x_in   = (const float*)d_in[0];
    const float* c_in   = (const float*)d_in[1];
    const float* enc_w1 = (const float*)d_in[2];
    const float* enc_b1 = (const float*)d_in[3];
    const float* enc_w2 = (const float*)d_in[4];
    const float* enc_b2 = (const float*)d_in[5];
    const float* mu0_w  = (const float*)d_in[6];
    const float* mu0_b  = (const float*)d_in[7];
    const float* lv0_w  = (const float*)d_in[8];
    const float* lv0_b  = (const float*)d_in[9];
    const float* mu1_w  = (const float*)d_in[10];
    const float* mu1_b  = (const float*)d_in[11];
    const float* lv1_w  = (const float*)d_in[12];
    const float* lv1_b  = (const float*)d_in[13];
    const float* dec_w  = (const float*)d_in[14];
    const float* dec_b  = (const float*)d_in[15];
    const float* gc0_w  = (const float*)d_in[16];
    const float* gc0_b  = (const float*)d_in[17];
    const float* gc1_w  = (const float*)d_in[18];
    const float* gc1_b  = (const float*)d_in[19];
    const float* fc_w   = (const float*)d_in[20];
    const float* fc_b   = (const float*)d_in[21];
    const float* reg_w  = (const float*)d_in[22];
    const float* reg_b  = (const float*)d_in[23];
    const float* W0     = (const float*)d_in[24];
    const float* b0v    = (const float*)d_in[25];
    const float* W1     = (const float*)d_in[26];
    const float* b1v    = (const float*)d_in[27];
    float* out = (float*)d_out;

    void *p;
    float *part1, *h1, *part2, *h2, *mu, *lv, *z, *eps, *dbuf, *gbuf, *pre, *pfc;
    cudaGetSymbolAddress(&p, g_part1); part1 = (float*)p;
    cudaGetSymbolAddress(&p, g_h1);    h1    = (float*)p;
    cudaGetSymbolAddress(&p, g_part2); part2 = (float*)p;
    cudaGetSymbolAddress(&p, g_h2);    h2    = (float*)p;
    cudaGetSymbolAddress(&p, g_mu);    mu    = (float*)p;
    cudaGetSymbolAddress(&p, g_lv);    lv    = (float*)p;
    cudaGetSymbolAddress(&p, g_z);     z     = (float*)p;
    cudaGetSymbolAddress(&p, g_eps);   eps   = (float*)p;
    cudaGetSymbolAddress(&p, g_d);     dbuf  = (float*)p;
    cudaGetSymbolAddress(&p, g_gg);    gbuf  = (float*)p;
    cudaGetSymbolAddress(&p, g_pre);   pre   = (float*)p;
    cudaGetSymbolAddress(&p, g_pfc);   pfc   = (float*)p;

    static int smem_set = 0;
    cudaFuncSetAttribute(gemm_fc_split, cudaFuncAttributeMaxDynamicSharedMemorySize,
                         FC_SMEM_BYTES);
    (void)smem_set;

    // noise
    eps_kernel<<<12, 256>>>(eps);

    // encoder
    gemm_tn_splitk<<<dim3(H2D/64, KS1), 256>>>(x_in, enc_w1, part1, H2D, NSQ, NSQ/KS1);
    reduce_act<true><<<(BATCH*H2D + 255)/256, 256>>>(part1, KS1, enc_b1, h1, H2D);
    gemm_tn_splitk<<<dim3(H1D/64, KS2), 256>>>(h1, enc_w2, part2, H1D, H2D, H2D/KS2);
    reduce_act<true><<<(BATCH*H1D + 255)/256, 256>>>(part2, KS2, enc_b2, h2, H1D);

    // heads
    heads_kernel<<<768, 256>>>(h2, c_in, mu0_w, mu0_b, lv0_w, lv0_b,
                               mu1_w, mu1_b, lv1_w, lv1_b, mu, lv);

    // reparameterize + z/log_q
    reparam_kernel<<<12, 256>>>(mu, lv, eps, z, out);

    // y regression
    y_kernel<<<BATCH, 32>>>(z, c_in, reg_w, reg_b, out);

    // decoder chain
    dec_kernel<<<dim3(LDEC, BATCH), NN>>>(z, dec_w, dec_b, dbuf);
    gc_kernel<<<dim3(LDEC, BATCH), NN>>>(dbuf, c_in, gc0_w, gc0_b, gc1_w, gc1_b, gbuf);
    outer_kernel<<<BATCH, 256>>>(gbuf, c_in, W0, b0v, W1, b1v, pre);

    // fc GEMM (group-selected, split-K, f32x2) + combine/exp
    gemm_fc_split<<<dim3(NSQ/FCBN, FCKS), 256, FC_SMEM_BYTES>>>(pre, fc_w, pfc);
    fc_combine<<<(BATCH*NSQ + 255)/256, 256>>>(pfc, fc_b, out + X_OFF);
}